// round 8
// baseline (speedup 1.0000x reference)
#include <cuda_runtime.h>
#include <cstdint>

// Problem constants (fixed by the reference)
#define B_ 16
#define H_ 100
#define W_ 100
#define C_ 256
#define R_ 128
#define P_ 7
#define CELLS (P_ * P_)   // 49

__device__ __forceinline__ float4 lerp4(float4 a, float4 b, float4 c, float4 d,
                                        float fx, float fy)
{
    float4 o;
    float top, bot;
    top = a.x + (b.x - a.x) * fx;  bot = c.x + (d.x - c.x) * fx;  o.x = top + (bot - top) * fy;
    top = a.y + (b.y - a.y) * fx;  bot = c.y + (d.y - c.y) * fx;  o.y = top + (bot - top) * fy;
    top = a.z + (b.z - a.z) * fx;  bot = c.z + (d.z - c.z) * fx;  o.z = top + (bot - top) * fy;
    top = a.w + (b.w - a.w) * fx;  bot = c.w + (d.w - c.w) * fx;  o.w = top + (bot - top) * fy;
    return o;
}

__device__ __forceinline__ float4 ldcg4(const float4* p)
{
    float4 v;
    asm volatile("ld.global.cg.v4.f32 {%0,%1,%2,%3}, [%4];"
                 : "=f"(v.x), "=f"(v.y), "=f"(v.z), "=f"(v.w) : "l"(p));
    return v;
}

// One CTA per ROI, 128 threads = (2 cell-lanes) x (64 float4 channel groups).
// Grid = 2048 CTAs at 16 CTAs/SM max -> the ENTIRE grid is one resident wave
// (148*16 = 2368 >= 2048): no wave-quantization tail, 52-56 warps/SM sustained.
// Phase 1: threads 0..48 compute each cell's bilinear tuple into smem.
// Phase 2: lane `sub` sweeps cells sub, sub+2, ... with the next tuple
// prefetched so the LDS sits off the LDG critical path.
__global__ __launch_bounds__(128, 16) void roi_pool_kernel(
    const float* __restrict__ fm,   // [B, H, W, C]
    const int*   __restrict__ rois, // [B, R, 4]  (x, y, h, w)
    float*       __restrict__ out)  // [B, R, P, P, C]
{
    __shared__ int4   s_off[CELLS];   // float4-unit offsets of the 4 corners
    __shared__ float2 s_fr[CELLS];    // (fx, fy)

    const int roi_idx = blockIdx.x;        // b*R + r
    const int b = roi_idx >> 7;            // R_ = 128
    const int tid = threadIdx.x;

    if (tid < CELLS) {
        const int4 roi = __ldg((const int4*)(rois + (size_t)roi_idx * 4));
        const int x = roi.x, y = roi.y, h = roi.z, w = roi.w;

        const int py = tid / P_;
        const int px = tid - py * P_;

        // y axis: src = (py+0.5)/P * h - 0.5, clipped to [0, h-1]
        const float hf = (float)h;
        float sy = ((float)py + 0.5f) * (1.0f / P_) * hf - 0.5f;
        sy = fminf(fmaxf(sy, 0.0f), hf - 1.0f);
        int   y0 = (int)floorf(sy);
        const float fy = sy - (float)y0;
        y0 += y;
        const int y1 = min(y0 + 1, y + h - 1);

        // x axis
        const float wf = (float)w;
        float sx = ((float)px + 0.5f) * (1.0f / P_) * wf - 0.5f;
        sx = fminf(fmaxf(sx, 0.0f), wf - 1.0f);
        int   x0 = (int)floorf(sx);
        const float fx = sx - (float)x0;
        x0 += x;
        const int x1 = min(x0 + 1, x + w - 1);

        // offsets in float4 units (C_/4 = 64 per pixel row)
        s_off[tid] = make_int4((y0 * W_ + x0) * (C_ / 4),
                               (y0 * W_ + x1) * (C_ / 4),
                               (y1 * W_ + x0) * (C_ / 4),
                               (y1 * W_ + x1) * (C_ / 4));
        s_fr[tid] = make_float2(fx, fy);
    }
    __syncthreads();

    const int c4  = tid & 63;     // float4 channel group 0..63
    const int sub = tid >> 6;     // cell lane 0..1

    const float4* base  = (const float4*)(fm + (size_t)b * (H_ * W_ * C_)) + c4;
    float4*       obase = (float4*)(out + (size_t)roi_idx * (CELLS * C_)) + c4;

    // Tuple for the first cell.
    int4   off = s_off[sub];
    float2 fr  = s_fr[sub];

    // Lane `sub` covers cells sub, sub+2, ..., sub+46 (24 cells).
    #pragma unroll 4
    for (int k = 0; k < 24; k++) {
        const int cell = sub + k * 2;

        // Prefetch next tuple before touching this cell's data.
        int4   noff;
        float2 nfr;
        if (k < 23) {
            noff = s_off[cell + 2];
            nfr  = s_fr[cell + 2];
        }

        const float4 a = ldcg4(base + off.x);
        const float4 bq = ldcg4(base + off.y);
        const float4 c = ldcg4(base + off.z);
        const float4 d = ldcg4(base + off.w);

        __stcs(obase + cell * (C_ / 4), lerp4(a, bq, c, d, fr.x, fr.y));

        if (k < 23) { off = noff; fr = nfr; }
    }

    // Remainder: cell 48 (lane 0 only).
    if (sub == 0) {
        const int4   roff = s_off[48];
        const float2 rfr  = s_fr[48];
        const float4 ra = ldcg4(base + roff.x);
        const float4 rb = ldcg4(base + roff.y);
        const float4 rc = ldcg4(base + roff.z);
        const float4 rd = ldcg4(base + roff.w);
        __stcs(obase + 48 * (C_ / 4), lerp4(ra, rb, rc, rd, rfr.x, rfr.y));
    }
}

extern "C" void kernel_launch(void* const* d_in, const int* in_sizes, int n_in,
                              void* d_out, int out_size)
{
    const float* fm   = (const float*)d_in[0];
    const int*   rois = (const int*)d_in[1];
    float*       out  = (float*)d_out;

    roi_pool_kernel<<<B_ * R_, 128>>>(fm, rois, out);
}

// round 9
// speedup vs baseline: 1.3692x; 1.3692x over previous
#include <cuda_runtime.h>
#include <cstdint>

// Problem constants (fixed by the reference)
#define B_ 16
#define H_ 100
#define W_ 100
#define C_ 256
#define R_ 128
#define P_ 7
#define CELLS (P_ * P_)   // 49

__device__ __forceinline__ float4 lerp4(float4 a, float4 b, float4 c, float4 d,
                                        float fx, float fy)
{
    float4 o;
    float top, bot;
    top = a.x + (b.x - a.x) * fx;  bot = c.x + (d.x - c.x) * fx;  o.x = top + (bot - top) * fy;
    top = a.y + (b.y - a.y) * fx;  bot = c.y + (d.y - c.y) * fx;  o.y = top + (bot - top) * fy;
    top = a.z + (b.z - a.z) * fx;  bot = c.z + (d.z - c.z) * fx;  o.z = top + (bot - top) * fy;
    top = a.w + (b.w - a.w) * fx;  bot = c.w + (d.w - c.w) * fx;  o.w = top + (bot - top) * fy;
    return o;
}

__device__ __forceinline__ float4 ldcg4(const float4* p)
{
    float4 v;
    asm volatile("ld.global.cg.v4.f32 {%0,%1,%2,%3}, [%4];"
                 : "=f"(v.x), "=f"(v.y), "=f"(v.z), "=f"(v.w) : "l"(p));
    return v;
}

// TWO CTAs per ROI (split by channel halves): grid = 4096, 256 threads each.
// Thread layout: 8 cell-lanes x 32 channel threads; each warp is one lane and
// loads 32 x 16B = 512B coalesced per corner. 8 CTAs/SM -> 3.46 waves (short
// CTAs, good tail backfill; the single-wave experiment of R8 regressed).
// Phase 1: threads 0..48 build the per-cell bilinear table in smem.
// Phase 2: lane `sub` sweeps cells sub, sub+8, ..., sub+40 (6 cells) with the
// next tuple prefetched; cell 48 handled by lane 0.
__global__ __launch_bounds__(256, 8) void roi_pool_kernel(
    const float* __restrict__ fm,   // [B, H, W, C]
    const int*   __restrict__ rois, // [B, R, 4]  (x, y, h, w)
    float*       __restrict__ out)  // [B, R, P, P, C]
{
    __shared__ int4   s_off[CELLS];   // float4-unit offsets of the 4 corners
    __shared__ float2 s_fr[CELLS];    // (fx, fy)

    const int roi_idx = blockIdx.x >> 1;        // b*R + r
    const int chalf   = blockIdx.x & 1;         // channel half 0/1
    const int b = roi_idx >> 7;                 // R_ = 128
    const int tid = threadIdx.x;

    if (tid < CELLS) {
        const int4 roi = __ldg((const int4*)(rois + (size_t)roi_idx * 4));
        const int x = roi.x, y = roi.y, h = roi.z, w = roi.w;

        const int py = tid / P_;
        const int px = tid - py * P_;

        // y axis: src = (py+0.5)/P * h - 0.5, clipped to [0, h-1]
        const float hf = (float)h;
        float sy = ((float)py + 0.5f) * (1.0f / P_) * hf - 0.5f;
        sy = fminf(fmaxf(sy, 0.0f), hf - 1.0f);
        int   y0 = (int)floorf(sy);
        const float fy = sy - (float)y0;
        y0 += y;
        const int y1 = min(y0 + 1, y + h - 1);

        // x axis
        const float wf = (float)w;
        float sx = ((float)px + 0.5f) * (1.0f / P_) * wf - 0.5f;
        sx = fminf(fmaxf(sx, 0.0f), wf - 1.0f);
        int   x0 = (int)floorf(sx);
        const float fx = sx - (float)x0;
        x0 += x;
        const int x1 = min(x0 + 1, x + w - 1);

        // offsets in float4 units (C_/4 = 64 per pixel row)
        s_off[tid] = make_int4((y0 * W_ + x0) * (C_ / 4),
                               (y0 * W_ + x1) * (C_ / 4),
                               (y1 * W_ + x0) * (C_ / 4),
                               (y1 * W_ + x1) * (C_ / 4));
        s_fr[tid] = make_float2(fx, fy);
    }
    __syncthreads();

    const int c4  = (tid & 31) + (chalf << 5);  // float4 channel group 0..63
    const int sub = tid >> 5;                   // cell lane 0..7 (= warp id)

    const float4* base  = (const float4*)(fm + (size_t)b * (H_ * W_ * C_)) + c4;
    float4*       obase = (float4*)(out + (size_t)roi_idx * (CELLS * C_)) + c4;

    // Tuple for the first cell.
    int4   off = s_off[sub];
    float2 fr  = s_fr[sub];

    // Lane `sub` covers cells sub, sub+8, ..., sub+40 (6 cells).
    #pragma unroll
    for (int k = 0; k < 6; k++) {
        const int cell = sub + k * 8;

        // Prefetch next tuple before touching this cell's data.
        int4   noff;
        float2 nfr;
        if (k < 5) {
            noff = s_off[cell + 8];
            nfr  = s_fr[cell + 8];
        }

        const float4 a = ldcg4(base + off.x);
        const float4 bq = ldcg4(base + off.y);
        const float4 c = ldcg4(base + off.z);
        const float4 d = ldcg4(base + off.w);

        __stcs(obase + cell * (C_ / 4), lerp4(a, bq, c, d, fr.x, fr.y));

        if (k < 5) { off = noff; fr = nfr; }
    }

    // Remainder: cell 48 (lane 0 only).
    if (sub == 0) {
        const int4   roff = s_off[48];
        const float2 rfr  = s_fr[48];
        const float4 ra = ldcg4(base + roff.x);
        const float4 rb = ldcg4(base + roff.y);
        const float4 rc = ldcg4(base + roff.z);
        const float4 rd = ldcg4(base + roff.w);
        __stcs(obase + 48 * (C_ / 4), lerp4(ra, rb, rc, rd, rfr.x, rfr.y));
    }
}

extern "C" void kernel_launch(void* const* d_in, const int* in_sizes, int n_in,
                              void* d_out, int out_size)
{
    const float* fm   = (const float*)d_in[0];
    const int*   rois = (const int*)d_in[1];
    float*       out  = (float*)d_out;

    roi_pool_kernel<<<B_ * R_ * 2, 256>>>(fm, rois, out);
}